// round 2
// baseline (speedup 1.0000x reference)
#include <cuda_runtime.h>
#include <math.h>

// ============================================================================
// CrossAttention: out = softmax((xWq+bq)(yWk+bk)^T / 8) (yWv+bv) Wo + bo
// B=4, SQ=SKV=2048, D_EMBED=1024, D_CROSS=768, H=16, DH=64
// All-fp32 round-0 implementation: tiled SGEMM + fp32 flash attention.
// ============================================================================

#define M_ROWS 8192        // B*SQ = B*SKV
#define N_ATT  1024        // D_ATT
#define HEADS  16
#define DHEAD  64
#define SEQ    2048

// Scratch: [B,H,S,DH] for q,k,v ; [B*S, D_ATT] for attn output
__device__ float g_q[8388608];
__device__ float g_k[8388608];
__device__ float g_v[8388608];
__device__ float g_attn[8388608];

// ----------------------------------------------------------------------------
// SGEMM: C = A(MxK) * B(KxN) + bias(N).  128x128 tile, BK=8, 256 threads,
// 8x8 per-thread micro-tile, double-buffered smem.
// mode 0: C row-major [M,N]
// mode 1: C written as [B,H,S,DH] scratch (head split) with m=b*2048+s, n=h*64+d
// ----------------------------------------------------------------------------
__global__ __launch_bounds__(256) void gemm_bias_kernel(
    const float* __restrict__ A, const float* __restrict__ B,
    const float* __restrict__ bias, float* __restrict__ C,
    int M, int N, int K, int mode)
{
    __shared__ float As[2][8][128];   // transposed: As[k][row]
    __shared__ float Bs[2][8][128];   // Bs[k][col]

    const int tid = threadIdx.x;
    const int ty  = tid >> 4;         // 0..15
    const int tx  = tid & 15;         // 0..15
    const int rowBase = blockIdx.y * 128;
    const int colBase = blockIdx.x * 128;

    const int ar = tid >> 1;          // 0..127
    const int ac = (tid & 1) << 2;    // 0 or 4
    const int br = tid >> 5;          // 0..7
    const int bc = (tid & 31) << 2;   // 0..124

    const float* Ag = A + (size_t)(rowBase + ar) * K + ac;
    const float* Bg = B + (size_t)br * N + colBase + bc;

    float acc[8][8];
    #pragma unroll
    for (int i = 0; i < 8; i++)
        #pragma unroll
        for (int j = 0; j < 8; j++) acc[i][j] = 0.f;

    // prologue: tile 0
    {
        float4 a4 = *(const float4*)Ag;
        float4 b4 = *(const float4*)Bg;
        As[0][ac+0][ar] = a4.x; As[0][ac+1][ar] = a4.y;
        As[0][ac+2][ar] = a4.z; As[0][ac+3][ar] = a4.w;
        *(float4*)&Bs[0][br][bc] = b4;
    }
    __syncthreads();

    const int nT = K >> 3;
    for (int t = 0; t < nT; t++) {
        const int cur = t & 1;
        const int nxt = cur ^ 1;
        float4 na, nb;
        const bool more = (t + 1 < nT);
        if (more) {
            na = *(const float4*)(Ag + (t + 1) * 8);
            nb = *(const float4*)(Bg + (size_t)(t + 1) * 8 * N);
        }
        #pragma unroll
        for (int k = 0; k < 8; k++) {
            float4 ra0 = *(const float4*)&As[cur][k][ty * 8];
            float4 ra1 = *(const float4*)&As[cur][k][ty * 8 + 4];
            float4 rb0 = *(const float4*)&Bs[cur][k][tx * 8];
            float4 rb1 = *(const float4*)&Bs[cur][k][tx * 8 + 4];
            float ra[8] = {ra0.x, ra0.y, ra0.z, ra0.w, ra1.x, ra1.y, ra1.z, ra1.w};
            float rb[8] = {rb0.x, rb0.y, rb0.z, rb0.w, rb1.x, rb1.y, rb1.z, rb1.w};
            #pragma unroll
            for (int i = 0; i < 8; i++)
                #pragma unroll
                for (int j = 0; j < 8; j++)
                    acc[i][j] += ra[i] * rb[j];
        }
        if (more) {
            As[nxt][ac+0][ar] = na.x; As[nxt][ac+1][ar] = na.y;
            As[nxt][ac+2][ar] = na.z; As[nxt][ac+3][ar] = na.w;
            *(float4*)&Bs[nxt][br][bc] = nb;
            __syncthreads();
        }
    }

    #pragma unroll
    for (int i = 0; i < 8; i++) {
        const int m = rowBase + ty * 8 + i;
        #pragma unroll
        for (int jj = 0; jj < 2; jj++) {
            const int n = colBase + tx * 8 + jj * 4;
            float4 v;
            v.x = acc[i][jj*4+0] + bias[n+0];
            v.y = acc[i][jj*4+1] + bias[n+1];
            v.z = acc[i][jj*4+2] + bias[n+2];
            v.w = acc[i][jj*4+3] + bias[n+3];
            if (mode == 0) {
                *(float4*)&C[(size_t)m * N + n] = v;
            } else {
                const int b = m >> 11, s = m & 2047;
                const int h = n >> 6, d = n & 63;
                const size_t off = (((size_t)(b * HEADS + h)) * SEQ + s) * DHEAD + d;
                *(float4*)&C[off] = v;
            }
        }
    }
}

// ----------------------------------------------------------------------------
// fp32 flash attention: per (b,h,qblock of 64). KV tiles of 64.
// smem: Qs[64][68] (pre-scaled), Kt[64 d][68 kv], Vs[64 kv][68 d], Ps[64][68]
// threads: 256 = 16x16, each thread owns a 4x4 tile of S / O.
// ----------------------------------------------------------------------------
#define SST 68
#define ATTN_SMEM (4 * 64 * SST * 4)

__global__ __launch_bounds__(256) void attn_kernel(
    const float* __restrict__ Qg_, const float* __restrict__ Kg_,
    const float* __restrict__ Vg_, float* __restrict__ Out)
{
    extern __shared__ float sm[];
    float* Qs = sm;
    float* Kt = sm + 64 * SST;
    float* Vs = sm + 2 * 64 * SST;
    float* Ps = sm + 3 * 64 * SST;

    const int tid = threadIdx.x;
    const int ty  = tid >> 4;
    const int tx  = tid & 15;
    const int qb  = blockIdx.x;   // 0..31
    const int h   = blockIdx.y;   // 0..15
    const int b   = blockIdx.z;   // 0..3

    const size_t headOff = ((size_t)(b * HEADS + h)) * SEQ * DHEAD;
    const float* Qg = Qg_ + headOff + (size_t)qb * 64 * DHEAD;
    const float* Kg = Kg_ + headOff;
    const float* Vg = Vg_ + headOff;

    // Load Q tile, pre-scaled by 1/sqrt(64)
    #pragma unroll
    for (int i = 0; i < 4; i++) {
        const int idx = tid + i * 256;
        const int r = idx >> 4;
        const int c = (idx & 15) << 2;
        float4 q4 = *(const float4*)(Qg + r * DHEAD + c);
        q4.x *= 0.125f; q4.y *= 0.125f; q4.z *= 0.125f; q4.w *= 0.125f;
        *(float4*)&Qs[r * SST + c] = q4;
    }

    float m_i[4], l_i[4], o[4][4];
    #pragma unroll
    for (int i = 0; i < 4; i++) {
        m_i[i] = -1e30f; l_i[i] = 0.f;
        #pragma unroll
        for (int j = 0; j < 4; j++) o[i][j] = 0.f;
    }

    for (int kv0 = 0; kv0 < SEQ; kv0 += 64) {
        __syncthreads();  // prev-iter PV done reading Vs/Ps; Qs visible (1st iter)
        #pragma unroll
        for (int i = 0; i < 4; i++) {
            const int idx = tid + i * 256;
            const int r = idx >> 4;
            const int c = (idx & 15) << 2;
            float4 k4 = *(const float4*)(Kg + (size_t)(kv0 + r) * DHEAD + c);
            Kt[(c + 0) * SST + r] = k4.x;
            Kt[(c + 1) * SST + r] = k4.y;
            Kt[(c + 2) * SST + r] = k4.z;
            Kt[(c + 3) * SST + r] = k4.w;
            float4 v4 = *(const float4*)(Vg + (size_t)(kv0 + r) * DHEAD + c);
            *(float4*)&Vs[r * SST + c] = v4;
        }
        __syncthreads();

        // S = (Q*scale) K^T : 4x4 per thread
        float s[4][4];
        #pragma unroll
        for (int i = 0; i < 4; i++)
            #pragma unroll
            for (int j = 0; j < 4; j++) s[i][j] = 0.f;

        #pragma unroll 16
        for (int d = 0; d < 64; d++) {
            const float4 kb = *(const float4*)&Kt[d * SST + tx * 4];
            const float q0 = Qs[(ty * 4 + 0) * SST + d];
            const float q1 = Qs[(ty * 4 + 1) * SST + d];
            const float q2 = Qs[(ty * 4 + 2) * SST + d];
            const float q3 = Qs[(ty * 4 + 3) * SST + d];
            s[0][0] += q0 * kb.x; s[0][1] += q0 * kb.y; s[0][2] += q0 * kb.z; s[0][3] += q0 * kb.w;
            s[1][0] += q1 * kb.x; s[1][1] += q1 * kb.y; s[1][2] += q1 * kb.z; s[1][3] += q1 * kb.w;
            s[2][0] += q2 * kb.x; s[2][1] += q2 * kb.y; s[2][2] += q2 * kb.z; s[2][3] += q2 * kb.w;
            s[3][0] += q3 * kb.x; s[3][1] += q3 * kb.y; s[3][2] += q3 * kb.z; s[3][3] += q3 * kb.w;
        }

        // online softmax; row reductions across the 16 tx lanes (half-warp)
        #pragma unroll
        for (int i = 0; i < 4; i++) {
            float mx = fmaxf(fmaxf(s[i][0], s[i][1]), fmaxf(s[i][2], s[i][3]));
            mx = fmaxf(mx, __shfl_xor_sync(0xffffffffu, mx, 1));
            mx = fmaxf(mx, __shfl_xor_sync(0xffffffffu, mx, 2));
            mx = fmaxf(mx, __shfl_xor_sync(0xffffffffu, mx, 4));
            mx = fmaxf(mx, __shfl_xor_sync(0xffffffffu, mx, 8));
            const float mnew = fmaxf(m_i[i], mx);
            const float corr = __expf(m_i[i] - mnew);
            const float p0 = __expf(s[i][0] - mnew);
            const float p1 = __expf(s[i][1] - mnew);
            const float p2 = __expf(s[i][2] - mnew);
            const float p3 = __expf(s[i][3] - mnew);
            float rs = p0 + p1 + p2 + p3;
            rs += __shfl_xor_sync(0xffffffffu, rs, 1);
            rs += __shfl_xor_sync(0xffffffffu, rs, 2);
            rs += __shfl_xor_sync(0xffffffffu, rs, 4);
            rs += __shfl_xor_sync(0xffffffffu, rs, 8);
            l_i[i] = l_i[i] * corr + rs;
            m_i[i] = mnew;
            o[i][0] *= corr; o[i][1] *= corr; o[i][2] *= corr; o[i][3] *= corr;
            *(float4*)&Ps[(ty * 4 + i) * SST + tx * 4] = make_float4(p0, p1, p2, p3);
        }
        __syncthreads();

        // O += P V
        #pragma unroll 16
        for (int d = 0; d < 64; d++) {
            const float4 vb = *(const float4*)&Vs[d * SST + tx * 4];
            const float p0 = Ps[(ty * 4 + 0) * SST + d];
            const float p1 = Ps[(ty * 4 + 1) * SST + d];
            const float p2 = Ps[(ty * 4 + 2) * SST + d];
            const float p3 = Ps[(ty * 4 + 3) * SST + d];
            o[0][0] += p0 * vb.x; o[0][1] += p0 * vb.y; o[0][2] += p0 * vb.z; o[0][3] += p0 * vb.w;
            o[1][0] += p1 * vb.x; o[1][1] += p1 * vb.y; o[1][2] += p1 * vb.z; o[1][3] += p1 * vb.w;
            o[2][0] += p2 * vb.x; o[2][1] += p2 * vb.y; o[2][2] += p2 * vb.z; o[2][3] += p2 * vb.w;
            o[3][0] += p3 * vb.x; o[3][1] += p3 * vb.y; o[3][2] += p3 * vb.z; o[3][3] += p3 * vb.w;
        }
    }

    // epilogue: normalize and write to [B*S, D_ATT] row-major (head interleave)
    #pragma unroll
    for (int i = 0; i < 4; i++) {
        const float inv = 1.0f / l_i[i];
        const int row = qb * 64 + ty * 4 + i;
        const size_t off = ((size_t)b * SEQ + row) * N_ATT + h * DHEAD + tx * 4;
        *(float4*)&Out[off] = make_float4(o[i][0] * inv, o[i][1] * inv,
                                          o[i][2] * inv, o[i][3] * inv);
    }
}

// ----------------------------------------------------------------------------
// Launch
// ----------------------------------------------------------------------------
extern "C" void kernel_launch(void* const* d_in, const int* in_sizes, int n_in,
                              void* d_out, int out_size)
{
    const float* x  = (const float*)d_in[0];   // [4,2048,1024]
    const float* y  = (const float*)d_in[1];   // [4,2048,768]
    const float* Wq = (const float*)d_in[2];   // [1024,1024]
    const float* bq = (const float*)d_in[3];
    const float* Wk = (const float*)d_in[4];   // [768,1024]
    const float* bk = (const float*)d_in[5];
    const float* Wv = (const float*)d_in[6];   // [768,1024]
    const float* bv = (const float*)d_in[7];
    const float* Wo = (const float*)d_in[8];   // [1024,1024]
    const float* bo = (const float*)d_in[9];
    float* out = (float*)d_out;

    float *gq, *gk, *gv, *ga;
    cudaGetSymbolAddress((void**)&gq, g_q);
    cudaGetSymbolAddress((void**)&gk, g_k);
    cudaGetSymbolAddress((void**)&gv, g_v);
    cudaGetSymbolAddress((void**)&ga, g_attn);

    dim3 blk(256);
    dim3 gGemm(N_ATT / 128, M_ROWS / 128);   // (8, 64)

    // Projections (head-split epilogue)
    gemm_bias_kernel<<<gGemm, blk>>>(x, Wq, bq, gq, M_ROWS, N_ATT, 1024, 1);
    gemm_bias_kernel<<<gGemm, blk>>>(y, Wk, bk, gk, M_ROWS, N_ATT, 768, 1);
    gemm_bias_kernel<<<gGemm, blk>>>(y, Wv, bv, gv, M_ROWS, N_ATT, 768, 1);

    // Flash attention
    cudaFuncSetAttribute(attn_kernel, cudaFuncAttributeMaxDynamicSharedMemorySize,
                         ATTN_SMEM);
    attn_kernel<<<dim3(SEQ / 64, HEADS, 4), blk, ATTN_SMEM>>>(gq, gk, gv, ga);

    // Output projection (plain row-major write to d_out)
    gemm_bias_kernel<<<gGemm, blk>>>(ga, Wo, bo, out, M_ROWS, N_ATT, 1024, 0);
}

// round 7
// speedup vs baseline: 2.8205x; 2.8205x over previous
#include <cuda_runtime.h>
#include <cuda_bf16.h>
#include <cstdint>
#include <math.h>

typedef __nv_bfloat16 bf16;
#define HEADS 16
#define DHEAD 64
#define SEQ   2048

// ---- scratch ----
constexpr size_t OXS = 0;                     // x split      [8192][1024]
constexpr size_t OYS = OXS + 8388608;         // y split      [8192][768]
constexpr size_t OWQ = OYS + 6291456;         // Wq^T [N][K]
constexpr size_t OWK = OWQ + 1048576;
constexpr size_t OWV = OWK + 786432;
constexpr size_t OWO = OWV + 786432;
constexpr size_t OQ  = OWO + 1048576;         // q  [64bh][2048][64]
constexpr size_t OK_ = OQ  + 8388608;         // k  [64bh][2048][64]
constexpr size_t OV  = OK_ + 8388608;         // v  [64bh][2048][64]
constexpr size_t OVT = OV  + 8388608;         // v^T [64bh][64][2048]
constexpr size_t OAT = OVT + 8388608;         // attn out [8192][1024]
constexpr size_t TOTE = OAT + 8388608;
__device__ bf16 g_h[TOTE];
__device__ bf16 g_l[TOTE];

// ---- helpers ----
__device__ __forceinline__ uint32_t smem_u32(const void* p) {
    uint32_t a;
    asm("{ .reg .u64 t; cvta.to.shared.u64 t, %1; cvt.u32.u64 %0, t; }" : "=r"(a) : "l"(p));
    return a;
}
#define CP16(dst, src) asm volatile("cp.async.cg.shared.global [%0], [%1], 16;" :: "r"(dst), "l"(src))
#define CP_COMMIT()    asm volatile("cp.async.commit_group;" ::: "memory")
#define CP_WAIT0()     asm volatile("cp.async.wait_group 0;" ::: "memory")
#define CP_WAIT1()     asm volatile("cp.async.wait_group 1;" ::: "memory")

__device__ __forceinline__ void ldm4(uint32_t* r, uint32_t a) {
    asm volatile("ldmatrix.sync.aligned.m8n8.x4.shared.b16 {%0,%1,%2,%3}, [%4];"
        : "=r"(r[0]), "=r"(r[1]), "=r"(r[2]), "=r"(r[3]) : "r"(a));
}
__device__ __forceinline__ void ldm2(uint32_t* r, uint32_t a) {
    asm volatile("ldmatrix.sync.aligned.m8n8.x2.shared.b16 {%0,%1}, [%2];"
        : "=r"(r[0]), "=r"(r[1]) : "r"(a));
}
__device__ __forceinline__ void mma16816(float* d, const uint32_t* a, const uint32_t* b) {
    asm volatile("mma.sync.aligned.m16n8k16.row.col.f32.bf16.bf16.f32 "
        "{%0,%1,%2,%3}, {%4,%5,%6,%7}, {%8,%9}, {%0,%1,%2,%3};"
        : "+f"(d[0]), "+f"(d[1]), "+f"(d[2]), "+f"(d[3])
        : "r"(a[0]), "r"(a[1]), "r"(a[2]), "r"(a[3]), "r"(b[0]), "r"(b[1]));
}
__device__ __forceinline__ void split2(float a, float b, uint32_t& hi, uint32_t& lo) {
    bf16 ha = __float2bfloat16_rn(a), hb = __float2bfloat16_rn(b);
    __nv_bfloat162 H, L;
    H.x = ha; H.y = hb;
    L.x = __float2bfloat16_rn(a - __bfloat162float(ha));
    L.y = __float2bfloat16_rn(b - __bfloat162float(hb));
    hi = *reinterpret_cast<uint32_t*>(&H);
    lo = *reinterpret_cast<uint32_t*>(&L);
}

// ---- elementwise split fp32 -> bf16 hi/lo ----
__global__ __launch_bounds__(256) void split_kernel(
    const float* __restrict__ src, bf16* __restrict__ h, bf16* __restrict__ l, int n4)
{
    int i = blockIdx.x * 256 + threadIdx.x;
    if (i >= n4) return;
    float4 v = reinterpret_cast<const float4*>(src)[i];
    uint32_t h0, l0, h1, l1;
    split2(v.x, v.y, h0, l0);
    split2(v.z, v.w, h1, l1);
    reinterpret_cast<uint2*>(h)[i] = make_uint2(h0, h1);
    reinterpret_cast<uint2*>(l)[i] = make_uint2(l0, l1);
}

// ---- weight transpose+split: W[K][N] fp32 -> Wt hi/lo [N][K] ----
__global__ void wtsplit_kernel(const float* __restrict__ W,
                               bf16* __restrict__ th, bf16* __restrict__ tl, int K, int N)
{
    __shared__ float t[32][33];
    int n0 = blockIdx.x * 32, k0 = blockIdx.y * 32;
    int tx = threadIdx.x, ty = threadIdx.y;
    for (int i = ty; i < 32; i += 8) t[i][tx] = W[(size_t)(k0 + i) * N + n0 + tx];
    __syncthreads();
    for (int i = ty; i < 32; i += 8) {
        float v = t[tx][i];
        bf16 h = __float2bfloat16_rn(v);
        size_t o = (size_t)(n0 + i) * K + k0 + tx;
        th[o] = h;
        tl[o] = __float2bfloat16_rn(v - __bfloat162float(h));
    }
}

// ---- V transpose (bf16): [bh][s][64] -> [bh][64][s] ----
__global__ void vtrans_kernel(const bf16* __restrict__ vh, const bf16* __restrict__ vl,
                              bf16* __restrict__ oh, bf16* __restrict__ ol)
{
    __shared__ bf16 th[32][33], tl[32][33];
    int bh = blockIdx.z;
    size_t ib = (size_t)bh * SEQ * DHEAD, ob = (size_t)bh * DHEAD * SEQ;
    int s0 = blockIdx.x * 32, d0 = blockIdx.y * 32;
    int tx = threadIdx.x, ty = threadIdx.y;
    for (int i = ty; i < 32; i += 8) {
        size_t o = ib + (size_t)(s0 + i) * DHEAD + d0 + tx;
        th[i][tx] = vh[o]; tl[i][tx] = vl[o];
    }
    __syncthreads();
    for (int i = ty; i < 32; i += 8) {
        size_t o = ob + (size_t)(d0 + i) * SEQ + s0 + tx;
        oh[o] = th[tx][i]; ol[o] = tl[tx][i];
    }
}

// ============================================================================
// GEMM on mma.sync: C[128x128] = A[M][K] * Wt[N][K]^T (+bias)
// 256 thr = 8 warps (2x4 grid of 64x32 warp tiles). K-chunk 64, double-buffer.
// mode 0: bf16 hi/lo head-split out (scale applied). mode 1: fp32 row-major.
// ============================================================================
#define SKB  144        // padded row stride bytes (72 bf16)
#define GA_AH 0
#define GA_AL 18432
#define GA_BH 36864
#define GA_BL 55296
#define GBUF  73728
#define GSM   147456

__global__ __launch_bounds__(256, 1) void gemm_mma_kernel(
    const bf16* __restrict__ Ah, const bf16* __restrict__ Al,
    const bf16* __restrict__ Bh, const bf16* __restrict__ Bl,
    const float* __restrict__ bias, bf16* __restrict__ oh, bf16* __restrict__ ol,
    float* __restrict__ of, int K, float scale, int mode)
{
    extern __shared__ __align__(16) char sm[];
    uint32_t sb = smem_u32(sm);
    const int tid = threadIdx.x, warp = tid >> 5, lane = tid & 31;
    const int wm = warp & 1, wn = warp >> 1;
    const int m0 = blockIdx.y * 128, n0 = blockIdx.x * 128;

    auto prefetch = [&](int t, int buf) {
        uint32_t base = sb + buf * GBUF;
        int k0 = t * 64;
        #pragma unroll
        for (int i = 0; i < 4; i++) {
            int g = tid + i * 256;
            int row = g >> 3, c8 = g & 7;
            uint32_t doff = row * SKB + c8 * 16;
            size_t sa = (size_t)(m0 + row) * K + k0 + c8 * 8;
            size_t sbv = (size_t)(n0 + row) * K + k0 + c8 * 8;
            CP16(base + GA_AH + doff, Ah + sa);
            CP16(base + GA_AL + doff, Al + sa);
            CP16(base + GA_BH + doff, Bh + sbv);
            CP16(base + GA_BL + doff, Bl + sbv);
        }
    };

    float acc[4][4][4];
    #pragma unroll
    for (int a = 0; a < 4; a++)
        #pragma unroll
        for (int b = 0; b < 4; b++)
            #pragma unroll
            for (int c = 0; c < 4; c++) acc[a][b][c] = 0.f;

    prefetch(0, 0); CP_COMMIT();
    const int nT = K >> 6;
    const int arow = wm * 64 + (lane & 7) + ((lane >> 3) & 1) * 8;
    const int acolh = (lane >> 4) * 8;
    const int brow = wn * 32 + (lane & 7);
    const int bcolh = ((lane >> 3) & 1) * 8;

    for (int t = 0; t < nT; t++) {
        if (t + 1 < nT) { prefetch(t + 1, (t + 1) & 1); CP_COMMIT(); CP_WAIT1(); }
        else CP_WAIT0();
        __syncthreads();
        uint32_t base = sb + (t & 1) * GBUF;
        #pragma unroll
        for (int ks = 0; ks < 4; ks++) {
            uint32_t ah[4][4], al[4][4];
            uint32_t ao = (ks * 16 + acolh) * 2;
            #pragma unroll
            for (int mi = 0; mi < 4; mi++) {
                ldm4(ah[mi], base + GA_AH + (arow + mi * 16) * SKB + ao);
                ldm4(al[mi], base + GA_AL + (arow + mi * 16) * SKB + ao);
            }
            uint32_t bo = (ks * 16 + bcolh) * 2;
            #pragma unroll
            for (int ni = 0; ni < 4; ni++) {
                uint32_t bh2[2], bl2[2];
                ldm2(bh2, base + GA_BH + (brow + ni * 8) * SKB + bo);
                ldm2(bl2, base + GA_BL + (brow + ni * 8) * SKB + bo);
                #pragma unroll
                for (int mi = 0; mi < 4; mi++) {
                    mma16816(acc[mi][ni], ah[mi], bh2);
                    mma16816(acc[mi][ni], al[mi], bh2);
                    mma16816(acc[mi][ni], ah[mi], bl2);
                }
            }
        }
        __syncthreads();
    }

    const int g = lane >> 2, c2 = (lane & 3) * 2;
    #pragma unroll
    for (int mi = 0; mi < 4; mi++) {
        const int r0 = m0 + wm * 64 + mi * 16 + g;
        #pragma unroll
        for (int ni = 0; ni < 4; ni++) {
            const int cc = n0 + wn * 32 + ni * 8 + c2;
            const float b0 = bias[cc], b1 = bias[cc + 1];
            if (mode == 0) {
                #pragma unroll
                for (int rr = 0; rr < 2; rr++) {
                    const int r = r0 + rr * 8;
                    float f0 = (acc[mi][ni][rr * 2 + 0] + b0) * scale;
                    float f1 = (acc[mi][ni][rr * 2 + 1] + b1) * scale;
                    uint32_t hi, lo;
                    split2(f0, f1, hi, lo);
                    const int bb = r >> 11, s = r & 2047, hh = cc >> 6, d = cc & 63;
                    size_t off = (((size_t)bb * HEADS + hh) * SEQ + s) * DHEAD + d;
                    *reinterpret_cast<uint32_t*>(&oh[off]) = hi;
                    *reinterpret_cast<uint32_t*>(&ol[off]) = lo;
                }
            } else {
                *reinterpret_cast<float2*>(&of[(size_t)r0 * 1024 + cc]) =
                    make_float2(acc[mi][ni][0] + b0, acc[mi][ni][1] + b1);
                *reinterpret_cast<float2*>(&of[(size_t)(r0 + 8) * 1024 + cc]) =
                    make_float2(acc[mi][ni][2] + b0, acc[mi][ni][3] + b1);
            }
        }
    }
}

// ============================================================================
// Flash attention on mma.sync: 128 q/CTA, 64-kv tiles, 8 warps (16 rows each).
// S and O in registers; P built in-register from S fragments.
// ============================================================================
#define AQH 0
#define AQL 18432
#define AKV 36864       // per-buffer: KH, KL, VH, VL each 9216 B
#define ABUF 36864
#define ASMT 110592

__global__ __launch_bounds__(256, 2) void attn_mma_kernel(
    const bf16* __restrict__ qh, const bf16* __restrict__ ql,
    const bf16* __restrict__ kh, const bf16* __restrict__ kl,
    const bf16* __restrict__ vth, const bf16* __restrict__ vtl,
    bf16* __restrict__ ath, bf16* __restrict__ atl)
{
    extern __shared__ __align__(16) char sm[];
    uint32_t sb = smem_u32(sm);
    const int tid = threadIdx.x, warp = tid >> 5, lane = tid & 31;
    const int qt = blockIdx.x, hd = blockIdx.y, bz = blockIdx.z;
    const int bhi = bz * HEADS + hd;

    const bf16* qhp = qh + ((size_t)bhi * SEQ + qt * 128) * DHEAD;
    const bf16* qlp = ql + ((size_t)bhi * SEQ + qt * 128) * DHEAD;
    const bf16* khp = kh + (size_t)bhi * SEQ * DHEAD;
    const bf16* klp = kl + (size_t)bhi * SEQ * DHEAD;
    const bf16* vhp = vth + (size_t)bhi * DHEAD * SEQ;
    const bf16* vlp = vtl + (size_t)bhi * DHEAD * SEQ;

    // Q tile -> smem
    #pragma unroll
    for (int i = 0; i < 4; i++) {
        int gi = tid + i * 256;
        int row = gi >> 3, c8 = gi & 7;
        uint32_t doff = row * SKB + c8 * 16;
        CP16(sb + AQH + doff, qhp + (size_t)row * DHEAD + c8 * 8);
        CP16(sb + AQL + doff, qlp + (size_t)row * DHEAD + c8 * 8);
    }
    CP_COMMIT();

    auto kvpf = [&](int it, int buf) {
        int s0 = it * 64;
        uint32_t base = sb + AKV + buf * ABUF;
        #pragma unroll
        for (int i = 0; i < 2; i++) {
            int gi = tid + i * 256;
            int row = gi >> 3, c8 = gi & 7;
            uint32_t doff = row * SKB + c8 * 16;
            CP16(base + doff,         khp + (size_t)(s0 + row) * DHEAD + c8 * 8);
            CP16(base + 9216 + doff,  klp + (size_t)(s0 + row) * DHEAD + c8 * 8);
            CP16(base + 18432 + doff, vhp + (size_t)row * SEQ + s0 + c8 * 8);
            CP16(base + 27648 + doff, vlp + (size_t)row * SEQ + s0 + c8 * 8);
        }
    };
    kvpf(0, 0); CP_COMMIT();

    float o[8][4];
    #pragma unroll
    for (int n = 0; n < 8; n++)
        #pragma unroll
        for (int c = 0; c < 4; c++) o[n][c] = 0.f;
    float m0r = -1e30f, m1r = -1e30f, l0 = 0.f, l1 = 0.f;

    const int arow = warp * 16 + (lane & 7) + ((lane >> 3) & 1) * 8;
    const int acolh = (lane >> 4) * 8;
    const int br = (lane & 7);
    const int bch = ((lane >> 3) & 1) * 8;

    for (int it = 0; it < 32; it++) {
        if (it + 1 < 32) { kvpf(it + 1, (it + 1) & 1); CP_COMMIT(); CP_WAIT1(); }
        else CP_WAIT0();
        __syncthreads();
        uint32_t kbh = sb + AKV + (it & 1) * ABUF;
        uint32_t kbl = kbh + 9216, vbh = kbh + 18432, vbl = kbh + 27648;

        // S = Q K^T  (16 x 64 per warp)
        float s[8][4];
        #pragma unroll
        for (int n = 0; n < 8; n++)
            #pragma unroll
            for (int c = 0; c < 4; c++) s[n][c] = 0.f;
        #pragma unroll
        for (int ks = 0; ks < 4; ks++) {
            uint32_t qhf[4], qlf[4];
            uint32_t ao = (ks * 16 + acolh) * 2;
            ldm4(qhf, sb + AQH + arow * SKB + ao);
            ldm4(qlf, sb + AQL + arow * SKB + ao);
            uint32_t bo = (ks * 16 + bch) * 2;
            #pragma unroll
            for (int ni = 0; ni < 8; ni++) {
                uint32_t bh2[2], bl2[2];
                ldm2(bh2, kbh + (ni * 8 + br) * SKB + bo);
                ldm2(bl2, kbl + (ni * 8 + br) * SKB + bo);
                mma16816(s[ni], qhf, bh2);
                mma16816(s[ni], qlf, bh2);
                mma16816(s[ni], qhf, bl2);
            }
        }

        // online softmax (rows g and g+8 of the warp strip)
        float mx0 = -1e30f, mx1 = -1e30f;
        #pragma unroll
        for (int n = 0; n < 8; n++) {
            mx0 = fmaxf(mx0, fmaxf(s[n][0], s[n][1]));
            mx1 = fmaxf(mx1, fmaxf(s[n][2], s[n][3]));
        }
        mx0 = fmaxf(mx0, __shfl_xor_sync(0xffffffffu, mx0, 1));
        mx0 = fmaxf(mx0, __shfl_xor_sync(0xffffffffu, mx0, 2));
        mx1 = fmaxf(mx1, __shfl_xor_sync(0xffffffffu, mx1, 1));
        mx1 = fmaxf(mx1, __shfl_xor_sync(0xffffffffu, mx1, 2));
        const float mn0 = fmaxf(m0r, mx0), mn1 = fmaxf(m1r, mx1);
        const float c0 = __expf(m0r - mn0), c1 = __expf(m1r - mn1);
        float rs0 = 0.f, rs1 = 0.f;
        #pragma unroll
        for (int n = 0; n < 8; n++) {
            s[n][0] = __expf(s[n][0] - mn0); s[n][1] = __expf(s[n][1] - mn0);
            s[n][2] = __expf(s[n][2] - mn1); s[n][3] = __expf(s[n][3] - mn1);
            rs0 += s[n][0] + s[n][1];
            rs1 += s[n][2] + s[n][3];
        }
        rs0 += __shfl_xor_sync(0xffffffffu, rs0, 1);
        rs0 += __shfl_xor_sync(0xffffffffu, rs0, 2);
        rs1 += __shfl_xor_sync(0xffffffffu, rs1, 1);
        rs1 += __shfl_xor_sync(0xffffffffu, rs1, 2);
        l0 = l0 * c0 + rs0; l1 = l1 * c1 + rs1;
        m0r = mn0; m1r = mn1;
        #pragma unroll
        for (int n = 0; n < 8; n++) {
            o[n][0] *= c0; o[n][1] *= c0; o[n][2] *= c1; o[n][3] *= c1;
        }

        // O += P V  (P from S regs: C-frag layout == A-frag layout)
        #pragma unroll
        for (int ks = 0; ks < 4; ks++) {
            uint32_t ph4[4], pl4[4];
            split2(s[2 * ks][0],     s[2 * ks][1],     ph4[0], pl4[0]);
            split2(s[2 * ks][2],     s[2 * ks][3],     ph4[1], pl4[1]);
            split2(s[2 * ks + 1][0], s[2 * ks + 1][1], ph4[2], pl4[2]);
            split2(s[2 * ks + 1][2], s[2 * ks + 1][3], ph4[3], pl4[3]);
            uint32_t bo = (ks * 16 + bch) * 2;
            #pragma unroll
            for (int ni = 0; ni < 8; ni++) {
                uint32_t bh2[2], bl2[2];
                ldm2(bh2, vbh + (ni * 8 + br) * SKB + bo);
                ldm2(bl2, vbl + (ni * 8 + br) * SKB + bo);
                mma16816(o[ni], ph4, bh2);
                mma16816(o[ni], pl4, bh2);
                mma16816(o[ni], ph4, bl2);
            }
        }
        __syncthreads();
    }

    // epilogue -> g_at hi/lo [B*S][1024]
    const float i0 = 1.f / l0, i1 = 1.f / l1;
    const int r0 = qt * 128 + warp * 16 + (lane >> 2);
    const size_t rowA = ((size_t)bz * SEQ + r0) * 1024 + hd * 64;
    const size_t rowB = rowA + (size_t)8 * 1024;
    #pragma unroll
    for (int ni = 0; ni < 8; ni++) {
        const int d0 = ni * 8 + (lane & 3) * 2;
        uint32_t hi, lo;
        split2(o[ni][0] * i0, o[ni][1] * i0, hi, lo);
        *reinterpret_cast<uint32_t*>(&ath[rowA + d0]) = hi;
        *reinterpret_cast<uint32_t*>(&atl[rowA + d0]) = lo;
        split2(o[ni][2] * i1, o[ni][3] * i1, hi, lo);
        *reinterpret_cast<uint32_t*>(&ath[rowB + d0]) = hi;
        *reinterpret_cast<uint32_t*>(&atl[rowB + d0]) = lo;
    }
}

// ---- launch ----
extern "C" void kernel_launch(void* const* d_in, const int* in_sizes, int n_in,
                              void* d_out, int out_size)
{
    const float* x  = (const float*)d_in[0];
    const float* y  = (const float*)d_in[1];
    const float* Wq = (const float*)d_in[2];
    const float* bq = (const float*)d_in[3];
    const float* Wk = (const float*)d_in[4];
    const float* bk = (const float*)d_in[5];
    const float* Wv = (const float*)d_in[6];
    const float* bv = (const float*)d_in[7];
    const float* Wo = (const float*)d_in[8];
    const float* bo = (const float*)d_in[9];
    float* out = (float*)d_out;

    bf16 *H, *L;
    cudaGetSymbolAddress((void**)&H, g_h);
    cudaGetSymbolAddress((void**)&L, g_l);

    cudaFuncSetAttribute(gemm_mma_kernel, cudaFuncAttributeMaxDynamicSharedMemorySize, GSM);
    cudaFuncSetAttribute(attn_mma_kernel, cudaFuncAttributeMaxDynamicSharedMemorySize, ASMT);

    split_kernel<<<8192, 256>>>(x, H + OXS, L + OXS, 2097152);
    split_kernel<<<6144, 256>>>(y, H + OYS, L + OYS, 1572864);
    wtsplit_kernel<<<dim3(32, 32), dim3(32, 8)>>>(Wq, H + OWQ, L + OWQ, 1024, 1024);
    wtsplit_kernel<<<dim3(32, 24), dim3(32, 8)>>>(Wk, H + OWK, L + OWK, 768, 1024);
    wtsplit_kernel<<<dim3(32, 24), dim3(32, 8)>>>(Wv, H + OWV, L + OWV, 768, 1024);
    wtsplit_kernel<<<dim3(32, 32), dim3(32, 8)>>>(Wo, H + OWO, L + OWO, 1024, 1024);

    dim3 gg(8, 64);
    gemm_mma_kernel<<<gg, 256, GSM>>>(H + OXS, L + OXS, H + OWQ, L + OWQ, bq,
                                      H + OQ, L + OQ, nullptr, 1024, 0.125f, 0);
    gemm_mma_kernel<<<gg, 256, GSM>>>(H + OYS, L + OYS, H + OWK, L + OWK, bk,
                                      H + OK_, L + OK_, nullptr, 768, 1.0f, 0);
    gemm_mma_kernel<<<gg, 256, GSM>>>(H + OYS, L + OYS, H + OWV, L + OWV, bv,
                                      H + OV, L + OV, nullptr, 768, 1.0f, 0);
    vtrans_kernel<<<dim3(64, 2, 64), dim3(32, 8)>>>(H + OV, L + OV, H + OVT, L + OVT);

    attn_mma_kernel<<<dim3(16, 16, 4), 256, ASMT>>>(H + OQ, L + OQ, H + OK_, L + OK_,
                                                    H + OVT, L + OVT, H + OAT, L + OAT);

    gemm_mma_kernel<<<gg, 256, GSM>>>(H + OAT, L + OAT, H + OWO, L + OWO, bo,
                                      nullptr, nullptr, out, 1024, 1.0f, 1);
}

// round 8
// speedup vs baseline: 3.1153x; 1.1045x over previous
#include <cuda_runtime.h>
#include <cuda_bf16.h>
#include <cstdint>
#include <math.h>

typedef __nv_bfloat16 bf16;
#define HEADS 16
#define DHEAD 64
#define SEQ   2048

// ---- scratch ----
constexpr size_t OXS = 0;                     // x split      [8192][1024]
constexpr size_t OYS = OXS + 8388608;         // y split      [8192][768]
constexpr size_t OWQ = OYS + 6291456;         // Wq^T [N][K]
constexpr size_t OWK = OWQ + 1048576;
constexpr size_t OWV = OWK + 786432;
constexpr size_t OWO = OWV + 786432;
constexpr size_t OQ  = OWO + 1048576;         // q  [64bh][2048][64]
constexpr size_t OK_ = OQ  + 8388608;         // k  [64bh][2048][64]
constexpr size_t OV  = OK_ + 8388608;         // v  [64bh][2048][64]
constexpr size_t OVT = OV  + 8388608;         // v^T [64bh][64][2048]
constexpr size_t OAT = OVT + 8388608;         // attn out [8192][1024]
constexpr size_t TOTE = OAT + 8388608;
__device__ bf16 g_h[TOTE];
__device__ bf16 g_l[TOTE];

// ---- helpers ----
__device__ __forceinline__ uint32_t smem_u32(const void* p) {
    uint32_t a;
    asm("{ .reg .u64 t; cvta.to.shared.u64 t, %1; cvt.u32.u64 %0, t; }" : "=r"(a) : "l"(p));
    return a;
}
#define CP16(dst, src) asm volatile("cp.async.cg.shared.global [%0], [%1], 16;" :: "r"(dst), "l"(src))
#define CP_COMMIT()    asm volatile("cp.async.commit_group;" ::: "memory")
#define CP_WAIT0()     asm volatile("cp.async.wait_group 0;" ::: "memory")
#define CP_WAIT1()     asm volatile("cp.async.wait_group 1;" ::: "memory")

__device__ __forceinline__ void ldm4(uint32_t* r, uint32_t a) {
    asm volatile("ldmatrix.sync.aligned.m8n8.x4.shared.b16 {%0,%1,%2,%3}, [%4];"
        : "=r"(r[0]), "=r"(r[1]), "=r"(r[2]), "=r"(r[3]) : "r"(a));
}
__device__ __forceinline__ void ldm2(uint32_t* r, uint32_t a) {
    asm volatile("ldmatrix.sync.aligned.m8n8.x2.shared.b16 {%0,%1}, [%2];"
        : "=r"(r[0]), "=r"(r[1]) : "r"(a));
}
__device__ __forceinline__ void mma16816(float* d, const uint32_t* a, const uint32_t* b) {
    asm volatile("mma.sync.aligned.m16n8k16.row.col.f32.bf16.bf16.f32 "
        "{%0,%1,%2,%3}, {%4,%5,%6,%7}, {%8,%9}, {%0,%1,%2,%3};"
        : "+f"(d[0]), "+f"(d[1]), "+f"(d[2]), "+f"(d[3])
        : "r"(a[0]), "r"(a[1]), "r"(a[2]), "r"(a[3]), "r"(b[0]), "r"(b[1]));
}
__device__ __forceinline__ float ex2(float x) {
    float r;
    asm("ex2.approx.f32 %0, %1;" : "=f"(r) : "f"(x));
    return r;
}
__device__ __forceinline__ void split2(float a, float b, uint32_t& hi, uint32_t& lo) {
    bf16 ha = __float2bfloat16_rn(a), hb = __float2bfloat16_rn(b);
    __nv_bfloat162 H, L;
    H.x = ha; H.y = hb;
    L.x = __float2bfloat16_rn(a - __bfloat162float(ha));
    L.y = __float2bfloat16_rn(b - __bfloat162float(hb));
    hi = *reinterpret_cast<uint32_t*>(&H);
    lo = *reinterpret_cast<uint32_t*>(&L);
}

// ---- elementwise split fp32 -> bf16 hi/lo ----
__global__ __launch_bounds__(256) void split_kernel(
    const float* __restrict__ src, bf16* __restrict__ h, bf16* __restrict__ l, int n4)
{
    int i = blockIdx.x * 256 + threadIdx.x;
    if (i >= n4) return;
    float4 v = reinterpret_cast<const float4*>(src)[i];
    uint32_t h0, l0, h1, l1;
    split2(v.x, v.y, h0, l0);
    split2(v.z, v.w, h1, l1);
    reinterpret_cast<uint2*>(h)[i] = make_uint2(h0, h1);
    reinterpret_cast<uint2*>(l)[i] = make_uint2(l0, l1);
}

// ---- weight transpose+split: W[K][N] fp32 -> Wt hi/lo [N][K] ----
__global__ void wtsplit_kernel(const float* __restrict__ W,
                               bf16* __restrict__ th, bf16* __restrict__ tl, int K, int N)
{
    __shared__ float t[32][33];
    int n0 = blockIdx.x * 32, k0 = blockIdx.y * 32;
    int tx = threadIdx.x, ty = threadIdx.y;
    for (int i = ty; i < 32; i += 8) t[i][tx] = W[(size_t)(k0 + i) * N + n0 + tx];
    __syncthreads();
    for (int i = ty; i < 32; i += 8) {
        float v = t[tx][i];
        bf16 h = __float2bfloat16_rn(v);
        size_t o = (size_t)(n0 + i) * K + k0 + tx;
        th[o] = h;
        tl[o] = __float2bfloat16_rn(v - __bfloat162float(h));
    }
}

// ---- V transpose (bf16): [bh][s][64] -> [bh][64][s] ----
__global__ void vtrans_kernel(const bf16* __restrict__ vh, const bf16* __restrict__ vl,
                              bf16* __restrict__ oh, bf16* __restrict__ ol)
{
    __shared__ bf16 th[32][33], tl[32][33];
    int bh = blockIdx.z;
    size_t ib = (size_t)bh * SEQ * DHEAD, ob = (size_t)bh * DHEAD * SEQ;
    int s0 = blockIdx.x * 32, d0 = blockIdx.y * 32;
    int tx = threadIdx.x, ty = threadIdx.y;
    for (int i = ty; i < 32; i += 8) {
        size_t o = ib + (size_t)(s0 + i) * DHEAD + d0 + tx;
        th[i][tx] = vh[o]; tl[i][tx] = vl[o];
    }
    __syncthreads();
    for (int i = ty; i < 32; i += 8) {
        size_t o = ob + (size_t)(d0 + i) * SEQ + s0 + tx;
        oh[o] = th[tx][i]; ol[o] = tl[tx][i];
    }
}

// ============================================================================
// GEMM on mma.sync: C[128x128] = A[M][K] * Wt[N][K]^T (+bias)
// K-chunk 32, XOR-swizzled 64B rows, 3-stage cp.async pipeline, 1 sync/iter,
// 2 CTAs/SM. 8 warps = 2x4 grid of 64x32 warp tiles.
// ============================================================================
#define GBUF 32768      // 4 matrices x 128 rows x 64B
#define GSM  98304      // 3 buffers

__global__ __launch_bounds__(256, 2) void gemm_mma_kernel(
    const bf16* __restrict__ Ah, const bf16* __restrict__ Al,
    const bf16* __restrict__ Bh, const bf16* __restrict__ Bl,
    const float* __restrict__ bias, bf16* __restrict__ oh, bf16* __restrict__ ol,
    float* __restrict__ of, int K, float scale, int mode)
{
    extern __shared__ __align__(16) char sm[];
    uint32_t sb = smem_u32(sm);
    const int tid = threadIdx.x, warp = tid >> 5, lane = tid & 31;
    const int wm = warp & 1, wn = warp >> 1;
    const int m0 = blockIdx.y * 128, n0 = blockIdx.x * 128;

    auto prefetch = [&](int t, int buf) {
        uint32_t base = sb + buf * GBUF;
        int k0 = t * 32;
        #pragma unroll
        for (int i = 0; i < 2; i++) {
            int g2 = tid + i * 256;           // 0..511
            int row = g2 >> 2, c8 = g2 & 3;
            uint32_t doff = row * 64 + (uint32_t)((c8 ^ ((row >> 1) & 3)) << 4);
            size_t sa  = (size_t)(m0 + row) * K + k0 + c8 * 8;
            size_t sbv = (size_t)(n0 + row) * K + k0 + c8 * 8;
            CP16(base + doff,         Ah + sa);
            CP16(base + 8192 + doff,  Al + sa);
            CP16(base + 16384 + doff, Bh + sbv);
            CP16(base + 24576 + doff, Bl + sbv);
        }
    };

    float acc[4][4][4];
    #pragma unroll
    for (int a = 0; a < 4; a++)
        #pragma unroll
        for (int b = 0; b < 4; b++)
            #pragma unroll
            for (int c = 0; c < 4; c++) acc[a][b][c] = 0.f;

    const int nT = K >> 5;
    prefetch(0, 0); CP_COMMIT();
    prefetch(1, 1); CP_COMMIT();

    const int arow0 = wm * 64 + (lane & 7) + ((lane >> 3) & 1) * 8;
    const int agk   = (lane >> 4) & 1;       // k-half for A ldm4
    const int brow0 = wn * 32 + (lane & 7);
    const int bgk   = (lane >> 3) & 1;       // k-half for B ldm2

    int buf = 0;
    for (int t = 0; t < nT; t++) {
        if (t < nT - 1) CP_WAIT1(); else CP_WAIT0();
        __syncthreads();                      // publishes stage t; guards buf reuse
        if (t + 2 < nT) { prefetch(t + 2, (buf + 2) % 3); CP_COMMIT(); }
        uint32_t base = sb + buf * GBUF;
        #pragma unroll
        for (int ks = 0; ks < 2; ks++) {
            uint32_t ah[4][4], al[4][4];
            const int gA = 2 * ks + agk;
            #pragma unroll
            for (int mi = 0; mi < 4; mi++) {
                const int rl = arow0 + mi * 16;
                uint32_t ad = base + rl * 64 + (uint32_t)((gA ^ ((rl >> 1) & 3)) << 4);
                ldm4(ah[mi], ad);
                ldm4(al[mi], ad + 8192);
            }
            const int gB = 2 * ks + bgk;
            #pragma unroll
            for (int ni = 0; ni < 4; ni++) {
                const int rl = brow0 + ni * 8;
                uint32_t bd = base + 16384 + rl * 64 + (uint32_t)((gB ^ ((rl >> 1) & 3)) << 4);
                uint32_t bh2[2], bl2[2];
                ldm2(bh2, bd);
                ldm2(bl2, bd + 8192);
                #pragma unroll
                for (int mi = 0; mi < 4; mi++) {
                    mma16816(acc[mi][ni], ah[mi], bh2);
                    mma16816(acc[mi][ni], al[mi], bh2);
                    mma16816(acc[mi][ni], ah[mi], bl2);
                }
            }
        }
        buf = (buf + 1) % 3;
    }

    const int g = lane >> 2, c2 = (lane & 3) * 2;
    #pragma unroll
    for (int mi = 0; mi < 4; mi++) {
        const int r0 = m0 + wm * 64 + mi * 16 + g;
        #pragma unroll
        for (int ni = 0; ni < 4; ni++) {
            const int cc = n0 + wn * 32 + ni * 8 + c2;
            const float b0 = bias[cc], b1 = bias[cc + 1];
            if (mode == 0) {
                #pragma unroll
                for (int rr = 0; rr < 2; rr++) {
                    const int r = r0 + rr * 8;
                    float f0 = (acc[mi][ni][rr * 2 + 0] + b0) * scale;
                    float f1 = (acc[mi][ni][rr * 2 + 1] + b1) * scale;
                    uint32_t hi, lo;
                    split2(f0, f1, hi, lo);
                    const int bb = r >> 11, s = r & 2047, hh = cc >> 6, d = cc & 63;
                    size_t off = (((size_t)bb * HEADS + hh) * SEQ + s) * DHEAD + d;
                    *reinterpret_cast<uint32_t*>(&oh[off]) = hi;
                    *reinterpret_cast<uint32_t*>(&ol[off]) = lo;
                }
            } else {
                *reinterpret_cast<float2*>(&of[(size_t)r0 * 1024 + cc]) =
                    make_float2(acc[mi][ni][0] + b0, acc[mi][ni][1] + b1);
                *reinterpret_cast<float2*>(&of[(size_t)(r0 + 8) * 1024 + cc]) =
                    make_float2(acc[mi][ni][2] + b0, acc[mi][ni][3] + b1);
            }
        }
    }
}

// ============================================================================
// Flash attention on mma.sync: 128 q/CTA, 64-kv tiles, 8 warps (16 rows each).
// Q pre-scaled by (1/8)*log2(e); softmax via ex2.approx.
// ============================================================================
#define SKB 144
#define AQH 0
#define AQL 18432
#define AKV 36864       // per-buffer: KH, KL, VH, VL each 9216 B
#define ABUF 36864
#define ASMT 110592

__global__ __launch_bounds__(256, 2) void attn_mma_kernel(
    const bf16* __restrict__ qh, const bf16* __restrict__ ql,
    const bf16* __restrict__ kh, const bf16* __restrict__ kl,
    const bf16* __restrict__ vth, const bf16* __restrict__ vtl,
    bf16* __restrict__ ath, bf16* __restrict__ atl)
{
    extern __shared__ __align__(16) char sm[];
    uint32_t sb = smem_u32(sm);
    const int tid = threadIdx.x, warp = tid >> 5, lane = tid & 31;
    const int qt = blockIdx.x, hd = blockIdx.y, bz = blockIdx.z;
    const int bhi = bz * HEADS + hd;

    const bf16* qhp = qh + ((size_t)bhi * SEQ + qt * 128) * DHEAD;
    const bf16* qlp = ql + ((size_t)bhi * SEQ + qt * 128) * DHEAD;
    const bf16* khp = kh + (size_t)bhi * SEQ * DHEAD;
    const bf16* klp = kl + (size_t)bhi * SEQ * DHEAD;
    const bf16* vhp = vth + (size_t)bhi * DHEAD * SEQ;
    const bf16* vlp = vtl + (size_t)bhi * DHEAD * SEQ;

    #pragma unroll
    for (int i = 0; i < 4; i++) {
        int gi = tid + i * 256;
        int row = gi >> 3, c8 = gi & 7;
        uint32_t doff = row * SKB + c8 * 16;
        CP16(sb + AQH + doff, qhp + (size_t)row * DHEAD + c8 * 8);
        CP16(sb + AQL + doff, qlp + (size_t)row * DHEAD + c8 * 8);
    }
    CP_COMMIT();

    auto kvpf = [&](int it, int buf) {
        int s0 = it * 64;
        uint32_t base = sb + AKV + buf * ABUF;
        #pragma unroll
        for (int i = 0; i < 2; i++) {
            int gi = tid + i * 256;
            int row = gi >> 3, c8 = gi & 7;
            uint32_t doff = row * SKB + c8 * 16;
            CP16(base + doff,         khp + (size_t)(s0 + row) * DHEAD + c8 * 8);
            CP16(base + 9216 + doff,  klp + (size_t)(s0 + row) * DHEAD + c8 * 8);
            CP16(base + 18432 + doff, vhp + (size_t)row * SEQ + s0 + c8 * 8);
            CP16(base + 27648 + doff, vlp + (size_t)row * SEQ + s0 + c8 * 8);
        }
    };
    kvpf(0, 0); CP_COMMIT();

    float o[8][4];
    #pragma unroll
    for (int n = 0; n < 8; n++)
        #pragma unroll
        for (int c = 0; c < 4; c++) o[n][c] = 0.f;
    float m0r = -1e30f, m1r = -1e30f, l0 = 0.f, l1 = 0.f;

    const int arow = warp * 16 + (lane & 7) + ((lane >> 3) & 1) * 8;
    const int acolh = (lane >> 4) * 8;
    const int br = (lane & 7);
    const int bch = ((lane >> 3) & 1) * 8;

    for (int it = 0; it < 32; it++) {
        if (it + 1 < 32) { kvpf(it + 1, (it + 1) & 1); CP_COMMIT(); CP_WAIT1(); }
        else CP_WAIT0();
        __syncthreads();
        uint32_t kbh = sb + AKV + (it & 1) * ABUF;
        uint32_t kbl = kbh + 9216, vbh = kbh + 18432, vbl = kbh + 27648;

        float s[8][4];
        #pragma unroll
        for (int n = 0; n < 8; n++)
            #pragma unroll
            for (int c = 0; c < 4; c++) s[n][c] = 0.f;
        #pragma unroll
        for (int ks = 0; ks < 4; ks++) {
            uint32_t qhf[4], qlf[4];
            uint32_t ao = (ks * 16 + acolh) * 2;
            ldm4(qhf, sb + AQH + arow * SKB + ao);
            ldm4(qlf, sb + AQL + arow * SKB + ao);
            uint32_t bo = (ks * 16 + bch) * 2;
            #pragma unroll
            for (int ni = 0; ni < 8; ni++) {
                uint32_t bh2[2], bl2[2];
                ldm2(bh2, kbh + (ni * 8 + br) * SKB + bo);
                ldm2(bl2, kbl + (ni * 8 + br) * SKB + bo);
                mma16816(s[ni], qhf, bh2);
                mma16816(s[ni], qlf, bh2);
                mma16816(s[ni], qhf, bl2);
            }
        }

        float mx0 = -1e30f, mx1 = -1e30f;
        #pragma unroll
        for (int n = 0; n < 8; n++) {
            mx0 = fmaxf(mx0, fmaxf(s[n][0], s[n][1]));
            mx1 = fmaxf(mx1, fmaxf(s[n][2], s[n][3]));
        }
        mx0 = fmaxf(mx0, __shfl_xor_sync(0xffffffffu, mx0, 1));
        mx0 = fmaxf(mx0, __shfl_xor_sync(0xffffffffu, mx0, 2));
        mx1 = fmaxf(mx1, __shfl_xor_sync(0xffffffffu, mx1, 1));
        mx1 = fmaxf(mx1, __shfl_xor_sync(0xffffffffu, mx1, 2));
        const float mn0 = fmaxf(m0r, mx0), mn1 = fmaxf(m1r, mx1);
        const float c0 = ex2(m0r - mn0), c1 = ex2(m1r - mn1);
        float rs0 = 0.f, rs1 = 0.f;
        #pragma unroll
        for (int n = 0; n < 8; n++) {
            s[n][0] = ex2(s[n][0] - mn0); s[n][1] = ex2(s[n][1] - mn0);
            s[n][2] = ex2(s[n][2] - mn1); s[n][3] = ex2(s[n][3] - mn1);
            rs0 += s[n][0] + s[n][1];
            rs1 += s[n][2] + s[n][3];
        }
        rs0 += __shfl_xor_sync(0xffffffffu, rs0, 1);
        rs0 += __shfl_xor_sync(0xffffffffu, rs0, 2);
        rs1 += __shfl_xor_sync(0xffffffffu, rs1, 1);
        rs1 += __shfl_xor_sync(0xffffffffu, rs1, 2);
        l0 = l0 * c0 + rs0; l1 = l1 * c1 + rs1;
        m0r = mn0; m1r = mn1;
        #pragma unroll
        for (int n = 0; n < 8; n++) {
            o[n][0] *= c0; o[n][1] *= c0; o[n][2] *= c1; o[n][3] *= c1;
        }

        #pragma unroll
        for (int ks = 0; ks < 4; ks++) {
            uint32_t ph4[4], pl4[4];
            split2(s[2 * ks][0],     s[2 * ks][1],     ph4[0], pl4[0]);
            split2(s[2 * ks][2],     s[2 * ks][3],     ph4[1], pl4[1]);
            split2(s[2 * ks + 1][0], s[2 * ks + 1][1], ph4[2], pl4[2]);
            split2(s[2 * ks + 1][2], s[2 * ks + 1][3], ph4[3], pl4[3]);
            uint32_t bo = (ks * 16 + bch) * 2;
            #pragma unroll
            for (int ni = 0; ni < 8; ni++) {
                uint32_t bh2[2], bl2[2];
                ldm2(bh2, vbh + (ni * 8 + br) * SKB + bo);
                ldm2(bl2, vbl + (ni * 8 + br) * SKB + bo);
                mma16816(o[ni], ph4, bh2);
                mma16816(o[ni], pl4, bh2);
                mma16816(o[ni], ph4, bl2);
            }
        }
        __syncthreads();
    }

    const float i0 = 1.f / l0, i1 = 1.f / l1;
    const int r0 = qt * 128 + warp * 16 + (lane >> 2);
    const size_t rowA = ((size_t)bz * SEQ + r0) * 1024 + hd * 64;
    const size_t rowB = rowA + (size_t)8 * 1024;
    #pragma unroll
    for (int ni = 0; ni < 8; ni++) {
        const int d0 = ni * 8 + (lane & 3) * 2;
        uint32_t hi, lo;
        split2(o[ni][0] * i0, o[ni][1] * i0, hi, lo);
        *reinterpret_cast<uint32_t*>(&ath[rowA + d0]) = hi;
        *reinterpret_cast<uint32_t*>(&atl[rowA + d0]) = lo;
        split2(o[ni][2] * i1, o[ni][3] * i1, hi, lo);
        *reinterpret_cast<uint32_t*>(&ath[rowB + d0]) = hi;
        *reinterpret_cast<uint32_t*>(&atl[rowB + d0]) = lo;
    }
}

// ---- launch ----
extern "C" void kernel_launch(void* const* d_in, const int* in_sizes, int n_in,
                              void* d_out, int out_size)
{
    const float* x  = (const float*)d_in[0];
    const float* y  = (const float*)d_in[1];
    const float* Wq = (const float*)d_in[2];
    const float* bq = (const float*)d_in[3];
    const float* Wk = (const float*)d_in[4];
    const float* bk = (const float*)d_in[5];
    const float* Wv = (const float*)d_in[6];
    const float* bv = (const float*)d_in[7];
    const float* Wo = (const float*)d_in[8];
    const float* bo = (const float*)d_in[9];
    float* out = (float*)d_out;

    bf16 *H, *L;
    cudaGetSymbolAddress((void**)&H, g_h);
    cudaGetSymbolAddress((void**)&L, g_l);

    cudaFuncSetAttribute(gemm_mma_kernel, cudaFuncAttributeMaxDynamicSharedMemorySize, GSM);
    cudaFuncSetAttribute(attn_mma_kernel, cudaFuncAttributeMaxDynamicSharedMemorySize, ASMT);

    split_kernel<<<8192, 256>>>(x, H + OXS, L + OXS, 2097152);
    split_kernel<<<6144, 256>>>(y, H + OYS, L + OYS, 1572864);
    wtsplit_kernel<<<dim3(32, 32), dim3(32, 8)>>>(Wq, H + OWQ, L + OWQ, 1024, 1024);
    wtsplit_kernel<<<dim3(32, 24), dim3(32, 8)>>>(Wk, H + OWK, L + OWK, 768, 1024);
    wtsplit_kernel<<<dim3(32, 24), dim3(32, 8)>>>(Wv, H + OWV, L + OWV, 768, 1024);
    wtsplit_kernel<<<dim3(32, 32), dim3(32, 8)>>>(Wo, H + OWO, L + OWO, 1024, 1024);

    // Q scale folds 1/sqrt(64) AND log2(e) so attention can use ex2 directly.
    const float qscale = 0.125f * 1.44269504088896341f;
    dim3 gg(8, 64);
    gemm_mma_kernel<<<gg, 256, GSM>>>(H + OXS, L + OXS, H + OWQ, L + OWQ, bq,
                                      H + OQ, L + OQ, nullptr, 1024, qscale, 0);
    gemm_mma_kernel<<<gg, 256, GSM>>>(H + OYS, L + OYS, H + OWK, L + OWK, bk,
                                      H + OK_, L + OK_, nullptr, 768, 1.0f, 0);
    gemm_mma_kernel<<<gg, 256, GSM>>>(H + OYS, L + OYS, H + OWV, L + OWV, bv,
                                      H + OV, L + OV, nullptr, 768, 1.0f, 0);
    vtrans_kernel<<<dim3(64, 2, 64), dim3(32, 8)>>>(H + OV, L + OV, H + OVT, L + OVT);

    attn_mma_kernel<<<dim3(16, 16, 4), 256, ASMT>>>(H + OQ, L + OQ, H + OK_, L + OK_,
                                                    H + OVT, L + OVT, H + OAT, L + OAT);

    gemm_mma_kernel<<<gg, 256, GSM>>>(H + OAT, L + OAT, H + OWO, L + OWO, bo,
                                      nullptr, nullptr, out, 1024, 1.0f, 1);
}